// round 1
// baseline (speedup 1.0000x reference)
#include <cuda_runtime.h>
#include <math.h>

// Problem constants
constexpr int Bb   = 8;
constexpr int T    = 1024;
constexpr int Dm   = 1024;
constexpr int NH   = 16;
constexpr int HD   = 64;
constexpr int FF   = 4096;
constexpr int MTOK = Bb * T;            // 8192 tokens

// ----------------------------------------------------------------------------
// Scratch (allocation-free: __device__ globals)
// ----------------------------------------------------------------------------
__device__ float g_xn[(size_t)MTOK * Dm];
__device__ float g_q [(size_t)MTOK * Dm];
__device__ float g_k [(size_t)MTOK * Dm];
__device__ float g_v [(size_t)MTOK * Dm];
__device__ float g_sc[(size_t)Bb * NH * T * T];       // 512 MB scores
__device__ float g_ao[(size_t)MTOK * Dm];             // attn_out [b,t,n,h]
__device__ float g_at[(size_t)MTOK * Dm];             // attn + residual
__device__ float g_ln[(size_t)MTOK * Dm];
__device__ float g_h1[(size_t)MTOK * FF];

// ----------------------------------------------------------------------------
// Reductions
// ----------------------------------------------------------------------------
__device__ __forceinline__ float warpSum(float v) {
    #pragma unroll
    for (int o = 16; o > 0; o >>= 1) v += __shfl_xor_sync(0xffffffffu, v, o);
    return v;
}
__device__ __forceinline__ float warpMax(float v) {
    #pragma unroll
    for (int o = 16; o > 0; o >>= 1) v = fmaxf(v, __shfl_xor_sync(0xffffffffu, v, o));
    return v;
}

// ----------------------------------------------------------------------------
// RMSNorm: one block per token row (D=1024, 256 thr x float4)
// ----------------------------------------------------------------------------
__global__ void __launch_bounds__(256) rmsnorm_k(const float* __restrict__ x,
                                                 const float* __restrict__ g,
                                                 float* __restrict__ out) {
    size_t base = (size_t)blockIdx.x * Dm;
    int tid = threadIdx.x;
    float4 xv = reinterpret_cast<const float4*>(x + base)[tid];
    float ss = xv.x * xv.x + xv.y * xv.y + xv.z * xv.z + xv.w * xv.w;

    __shared__ float sh[8];
    __shared__ float bval;
    ss = warpSum(ss);
    if ((tid & 31) == 0) sh[tid >> 5] = ss;
    __syncthreads();
    if (tid == 0) {
        float s = 0.f;
        #pragma unroll
        for (int i = 0; i < 8; i++) s += sh[i];
        bval = s;
    }
    __syncthreads();
    float r = rsqrtf(bval * (1.0f / Dm) + 1e-6f);
    float4 gv = reinterpret_cast<const float4*>(g)[tid];
    float4 ov = make_float4(xv.x * r * gv.x, xv.y * r * gv.y,
                            xv.z * r * gv.z, xv.w * r * gv.w);
    reinterpret_cast<float4*>(out + base)[tid] = ov;
}

// ----------------------------------------------------------------------------
// LayerNorm: one block per token row
// ----------------------------------------------------------------------------
__global__ void __launch_bounds__(256) layernorm_k(const float* __restrict__ x,
                                                   const float* __restrict__ gamma,
                                                   const float* __restrict__ beta,
                                                   float* __restrict__ out) {
    size_t base = (size_t)blockIdx.x * Dm;
    int tid = threadIdx.x;
    float4 xv = reinterpret_cast<const float4*>(x + base)[tid];
    float s1 = xv.x + xv.y + xv.z + xv.w;
    float s2 = xv.x * xv.x + xv.y * xv.y + xv.z * xv.z + xv.w * xv.w;

    __shared__ float shA[8], shB[8];
    __shared__ float bm, bv2;
    s1 = warpSum(s1);
    s2 = warpSum(s2);
    if ((tid & 31) == 0) { shA[tid >> 5] = s1; shB[tid >> 5] = s2; }
    __syncthreads();
    if (tid == 0) {
        float a = 0.f, b = 0.f;
        #pragma unroll
        for (int i = 0; i < 8; i++) { a += shA[i]; b += shB[i]; }
        bm = a * (1.0f / Dm);
        bv2 = b * (1.0f / Dm);
    }
    __syncthreads();
    float mean = bm;
    float var  = bv2 - mean * mean;
    float r = rsqrtf(var + 1e-5f);
    float4 gv = reinterpret_cast<const float4*>(gamma)[tid];
    float4 bvv = reinterpret_cast<const float4*>(beta)[tid];
    float4 ov = make_float4((xv.x - mean) * r * gv.x + bvv.x,
                            (xv.y - mean) * r * gv.y + bvv.y,
                            (xv.z - mean) * r * gv.z + bvv.z,
                            (xv.w - mean) * r * gv.w + bvv.w);
    reinterpret_cast<float4*>(out + base)[tid] = ov;
}

// ----------------------------------------------------------------------------
// Masked softmax over score rows (causal + padding), in-place.
// grid: (T, B*NH), block 256. Row length T=1024 (float4 per thread).
// ----------------------------------------------------------------------------
__global__ void __launch_bounds__(256) softmax_k(float* __restrict__ sc,
                                                 const float* __restrict__ padding) {
    int t = blockIdx.x;
    int z = blockIdx.y;            // b*NH + n
    int b = z >> 4;
    float* row = sc + ((size_t)z * T + t) * T;
    int tid = threadIdx.x;
    int s0 = tid * 4;

    float4 rv = reinterpret_cast<float4*>(row)[tid];
    float4 pv = reinterpret_cast<const float4*>(padding + (size_t)b * T)[tid];
    float padt = padding[(size_t)b * T + t];

    float vals[4] = {rv.x, rv.y, rv.z, rv.w};
    float pads[4] = {pv.x, pv.y, pv.z, pv.w};
    float mx = -3.4e38f;
    #pragma unroll
    for (int i = 0; i < 4; i++) {
        bool ok = (s0 + i <= t) && (padt != 0.f) && (pads[i] != 0.f);
        vals[i] = ok ? vals[i] : -1e9f;
        mx = fmaxf(mx, vals[i]);
    }

    __shared__ float sh[8];
    __shared__ float bmax, bsum;
    mx = warpMax(mx);
    if ((tid & 31) == 0) sh[tid >> 5] = mx;
    __syncthreads();
    if (tid == 0) {
        float m = sh[0];
        #pragma unroll
        for (int i = 1; i < 8; i++) m = fmaxf(m, sh[i]);
        bmax = m;
    }
    __syncthreads();
    mx = bmax;

    float e[4], ls = 0.f;
    #pragma unroll
    for (int i = 0; i < 4; i++) { e[i] = __expf(vals[i] - mx); ls += e[i]; }
    ls = warpSum(ls);
    if ((tid & 31) == 0) sh[tid >> 5] = ls;
    __syncthreads();
    if (tid == 0) {
        float s = 0.f;
        #pragma unroll
        for (int i = 0; i < 8; i++) s += sh[i];
        bsum = s;
    }
    __syncthreads();
    float inv = 1.0f / bsum;
    reinterpret_cast<float4*>(row)[tid] =
        make_float4(e[0] * inv, e[1] * inv, e[2] * inv, e[3] * inv);
}

// ----------------------------------------------------------------------------
// Generic tiled SGEMM: C = A(MxK) * B(+epilogue), 64x64x16 tile, 4x4 microtile.
// A row-major (lda). B: TB=false -> B[k*ldb+n]; TB=true -> B[n*ldb+k].
// Two-level batch: z -> (z/zdiv, z%zdiv) with per-level strides.
// Epilogue (runtime): +bias[n], *qscale(softplus per-dim, n&63), ReLU,
//                     +resid[m*ldc+n] (resid shares C's batch offset).
// causal: skip blocks entirely above the diagonal (C[m,n]=scores[t,s], skip n0>m0+63).
// All dims assumed multiples of tile sizes (true for this problem).
// ----------------------------------------------------------------------------
template <bool TB>
__global__ void __launch_bounds__(256) gemm_k(
    const float* __restrict__ A, const float* __restrict__ B, float* __restrict__ C,
    int M, int N, int K, int lda, int ldb, int ldc,
    int zdiv,
    long long sA1, long long sA2, long long sB1, long long sB2,
    long long sC1, long long sC2,
    const float* __restrict__ bias, const float* __restrict__ resid,
    const float* __restrict__ pds, int relu, int causal)
{
    int m0 = blockIdx.y * 64;
    int n0 = blockIdx.x * 64;
    if (causal && n0 > m0 + 63) return;   // fully-masked score tile

    int z  = blockIdx.z;
    int z1 = z / zdiv, z2 = z - z1 * zdiv;
    long long oA = (long long)z1 * sA1 + (long long)z2 * sA2;
    long long oB = (long long)z1 * sB1 + (long long)z2 * sB2;
    long long oC = (long long)z1 * sC1 + (long long)z2 * sC2;
    A += oA; B += oB; C += oC;
    const float* R = resid ? resid + oC : nullptr;

    __shared__ float As[16][68];
    __shared__ float Bs[16][68];

    int tid = threadIdx.x;
    int tx = tid & 15, ty = tid >> 4;
    int am = tid >> 2, ak = (tid & 3) * 4;

    float acc[4][4] = {};

    for (int k0 = 0; k0 < K; k0 += 16) {
        float4 av = *reinterpret_cast<const float4*>(
            A + (long long)(m0 + am) * lda + k0 + ak);
        As[ak + 0][am] = av.x; As[ak + 1][am] = av.y;
        As[ak + 2][am] = av.z; As[ak + 3][am] = av.w;

        if (TB) {
            float4 bv = *reinterpret_cast<const float4*>(
                B + (long long)(n0 + am) * ldb + k0 + ak);
            Bs[ak + 0][am] = bv.x; Bs[ak + 1][am] = bv.y;
            Bs[ak + 2][am] = bv.z; Bs[ak + 3][am] = bv.w;
        } else {
            int bk = tid >> 4, bn = (tid & 15) * 4;
            float4 bv = *reinterpret_cast<const float4*>(
                B + (long long)(k0 + bk) * ldb + n0 + bn);
            *reinterpret_cast<float4*>(&Bs[bk][bn]) = bv;
        }
        __syncthreads();

        #pragma unroll
        for (int kk = 0; kk < 16; kk++) {
            float4 a4 = *reinterpret_cast<const float4*>(&As[kk][ty * 4]);
            float4 b4 = *reinterpret_cast<const float4*>(&Bs[kk][tx * 4]);
            float aa[4] = {a4.x, a4.y, a4.z, a4.w};
            float bb[4] = {b4.x, b4.y, b4.z, b4.w};
            #pragma unroll
            for (int i = 0; i < 4; i++)
                #pragma unroll
                for (int j = 0; j < 4; j++)
                    acc[i][j] += aa[i] * bb[j];
        }
        __syncthreads();
    }

    // epilogue
    float qs[4] = {1.f, 1.f, 1.f, 1.f};
    if (pds) {
        #pragma unroll
        for (int j = 0; j < 4; j++) {
            int n = n0 + tx * 4 + j;
            float p = pds[n & (HD - 1)];
            float sp = (p > 20.f) ? p : log1pf(expf(p));
            qs[j] = 0.1803368801111f * sp;   // log2(e)/sqrt(64) * softplus
        }
    }
    #pragma unroll
    for (int i = 0; i < 4; i++) {
        int m = m0 + ty * 4 + i;
        #pragma unroll
        for (int j = 0; j < 4; j++) {
            int n = n0 + tx * 4 + j;
            float v = acc[i][j];
            if (bias) v += bias[n];
            if (pds)  v *= qs[j];
            if (relu) v = fmaxf(v, 0.f);
            if (R)    v += R[(long long)m * ldc + n];
            C[(long long)m * ldc + n] = v;
        }
    }
}

// ----------------------------------------------------------------------------
// Launch
// ----------------------------------------------------------------------------
extern "C" void kernel_launch(void* const* d_in, const int* in_sizes, int n_in,
                              void* d_out, int out_size) {
    const float* x    = (const float*)d_in[0];
    const float* pad  = (const float*)d_in[1];
    const float* rmss = (const float*)d_in[2];
    const float* pds  = (const float*)d_in[3];
    const float* wq   = (const float*)d_in[4];
    const float* bq   = (const float*)d_in[5];
    const float* wk   = (const float*)d_in[6];
    const float* bk   = (const float*)d_in[7];
    const float* wv   = (const float*)d_in[8];
    const float* bv   = (const float*)d_in[9];
    const float* wo   = (const float*)d_in[10];
    const float* bo   = (const float*)d_in[11];
    const float* lng  = (const float*)d_in[12];
    const float* lnb  = (const float*)d_in[13];
    const float* w1   = (const float*)d_in[14];
    const float* b1   = (const float*)d_in[15];
    const float* w2   = (const float*)d_in[16];
    const float* b2   = (const float*)d_in[17];
    float* out = (float*)d_out;

    float *xn, *q, *k, *v, *sc, *ao, *at, *ln, *h1;
    cudaGetSymbolAddress((void**)&xn, g_xn);
    cudaGetSymbolAddress((void**)&q,  g_q);
    cudaGetSymbolAddress((void**)&k,  g_k);
    cudaGetSymbolAddress((void**)&v,  g_v);
    cudaGetSymbolAddress((void**)&sc, g_sc);
    cudaGetSymbolAddress((void**)&ao, g_ao);
    cudaGetSymbolAddress((void**)&at, g_at);
    cudaGetSymbolAddress((void**)&ln, g_ln);
    cudaGetSymbolAddress((void**)&h1, g_h1);

    const long long Z = 0;

    // 1. RMSNorm
    rmsnorm_k<<<MTOK, 256>>>(x, rmss, xn);

    // 2. Q/K/V projections (Q fuses per-dim softplus scale)
    gemm_k<false><<<dim3(Dm / 64, MTOK / 64, 1), 256>>>(
        xn, wq, q, MTOK, Dm, Dm, Dm, Dm, Dm,
        1, Z, Z, Z, Z, Z, Z, bq, nullptr, pds, 0, 0);
    gemm_k<false><<<dim3(Dm / 64, MTOK / 64, 1), 256>>>(
        xn, wk, k, MTOK, Dm, Dm, Dm, Dm, Dm,
        1, Z, Z, Z, Z, Z, Z, bk, nullptr, nullptr, 0, 0);
    gemm_k<false><<<dim3(Dm / 64, MTOK / 64, 1), 256>>>(
        xn, wv, v, MTOK, Dm, Dm, Dm, Dm, Dm,
        1, Z, Z, Z, Z, Z, Z, bv, nullptr, nullptr, 0, 0);

    // 3. scores[b,n,t,s] = Q . K^T  (batched over b,n; causal tile skip)
    gemm_k<true><<<dim3(T / 64, T / 64, Bb * NH), 256>>>(
        q, k, sc, T, T, HD, Dm, Dm, T,
        NH,
        (long long)T * Dm, (long long)HD,     // A: b-stride, n-stride
        (long long)T * Dm, (long long)HD,     // B: b-stride, n-stride
        (long long)NH * T * T, (long long)T * T,
        nullptr, nullptr, nullptr, 0, 1);

    // 4. masked softmax (causal + padding), in place
    softmax_k<<<dim3(T, Bb * NH), 256>>>(sc, pad);

    // 5. attn_out[b,t,n,h] = P . V  (batched over b,n)
    gemm_k<false><<<dim3(HD / 64, T / 64, Bb * NH), 256>>>(
        sc, v, ao, T, HD, T, T, Dm, Dm,
        NH,
        (long long)NH * T * T, (long long)T * T,
        (long long)T * Dm, (long long)HD,
        (long long)T * Dm, (long long)HD,
        nullptr, nullptr, nullptr, 0, 0);

    // 6. output projection + bo + residual(x)
    gemm_k<true><<<dim3(Dm / 64, MTOK / 64, 1), 256>>>(
        ao, wo, at, MTOK, Dm, Dm, Dm, Dm, Dm,
        1, Z, Z, Z, Z, Z, Z, bo, x, nullptr, 0, 0);

    // 7. LayerNorm
    layernorm_k<<<MTOK, 256>>>(at, lng, lnb, ln);

    // 8. FFN1 + ReLU
    gemm_k<false><<<dim3(FF / 64, MTOK / 64, 1), 256>>>(
        ln, w1, h1, MTOK, FF, Dm, Dm, FF, FF,
        1, Z, Z, Z, Z, Z, Z, b1, nullptr, nullptr, 1, 0);

    // 9. FFN2 + b2 + residual(attn) -> d_out
    gemm_k<false><<<dim3(Dm / 64, MTOK / 64, 1), 256>>>(
        h1, w2, out, MTOK, Dm, FF, FF, Dm, Dm,
        1, Z, Z, Z, Z, Z, Z, b2, at, nullptr, 0, 0);
}

// round 6
// speedup vs baseline: 2.9417x; 2.9417x over previous
#include <cuda_runtime.h>
#include <math.h>
#include <stdint.h>

// Problem constants
constexpr int Bb   = 8;
constexpr int T    = 1024;
constexpr int Dm   = 1024;
constexpr int NH   = 16;
constexpr int HD   = 64;
constexpr int FF   = 4096;
constexpr int MTOK = Bb * T;            // 8192 tokens

// ----------------------------------------------------------------------------
// Scratch (allocation-free: __device__ globals)
// ----------------------------------------------------------------------------
__device__ __align__(256) float g_xn[(size_t)MTOK * Dm];
__device__ __align__(256) float g_q [(size_t)MTOK * Dm];
__device__ __align__(256) float g_k [(size_t)MTOK * Dm];
__device__ __align__(256) float g_v [(size_t)MTOK * Dm];
__device__ __align__(256) float g_sc[(size_t)Bb * NH * T * T];   // 512 MB scores
__device__ __align__(256) float g_ao[(size_t)MTOK * Dm];
__device__ __align__(256) float g_at[(size_t)MTOK * Dm];
__device__ __align__(256) float g_ln[(size_t)MTOK * Dm];
__device__ __align__(256) float g_h1[(size_t)MTOK * FF];

// ----------------------------------------------------------------------------
// Baseline-PTX helpers (no 'a'-gated instructions — harness compiles compute_103)
// ----------------------------------------------------------------------------
__device__ __forceinline__ uint32_t smem_u32(const void* p) {
    uint32_t a;
    asm("{ .reg .u64 t; cvta.to.shared.u64 t, %1; cvt.u32.u64 %0, t; }" : "=r"(a) : "l"(p));
    return a;
}
__device__ __forceinline__ void cpa16(void* dst, const void* src) {
    uint32_t d = smem_u32(dst);
    asm volatile("cp.async.cg.shared.global [%0], [%1], 16;" :: "r"(d), "l"(src) : "memory");
}
__device__ __forceinline__ uint32_t f2tf(float f) {
    uint32_t u;
    asm("cvt.rna.tf32.f32 %0, %1;" : "=r"(u) : "f"(f));
    return u;
}
__device__ __forceinline__ void mma8(float* c, const uint32_t* a, uint32_t b0, uint32_t b1) {
    asm volatile(
        "mma.sync.aligned.m16n8k8.row.col.f32.tf32.tf32.f32 "
        "{%0,%1,%2,%3}, {%4,%5,%6,%7}, {%8,%9}, {%0,%1,%2,%3};"
        : "+f"(c[0]), "+f"(c[1]), "+f"(c[2]), "+f"(c[3])
        : "r"(a[0]), "r"(a[1]), "r"(a[2]), "r"(a[3]), "r"(b0), "r"(b1));
}

// ----------------------------------------------------------------------------
// Tensor-core (mma.sync tf32) GEMM
// C[128 x BN] per CTA, K slab 32, double-buffered cp.async.
// A row-major [m][k]. B: TB=false -> B[k][n] (ldb); TB=true -> B[n][k] (ldb).
// Two-level batch z -> (z/zdiv, z%zdiv) with elementwise strides.
// Epilogue: +bias[n], *softplus-q-scale(n&63), ReLU, +resid (C-strided).
// causal:   skip C tiles fully above the diagonal (scores GEMM).
// causalK:  clamp K loop to m0+BM (PV GEMM; P is exactly 0 for s > t).
// ----------------------------------------------------------------------------
constexpr int BM = 128;
constexpr int BK = 32;

template <int BN, bool TB>
__global__ void __launch_bounds__(256) gemm_mma(
    const float* __restrict__ A, const float* __restrict__ B, float* __restrict__ C,
    int K, int lda, int ldb, int ldc, int zdiv,
    long long sA1, long long sA2, long long sB1, long long sB2,
    long long sC1, long long sC2,
    const float* __restrict__ bias, const float* __restrict__ resid,
    const float* __restrict__ pds, int relu, int causal, int causalK)
{
    constexpr int AW = BK + 4;                 // A row words (pad 4 -> conflict-free frags)
    constexpr int BW = TB ? (BK + 4) : (BN + 8);
    constexpr int AS = BM * AW;
    constexpr int BS = TB ? BN * BW : BK * BW;
    constexpr int STW = AS + BS;               // words per stage
    constexpr int NT = BN / 16;                // n-tiles per warp (warp covers BN/2 cols)
    extern __shared__ float sm[];

    int m0 = blockIdx.y * BM;
    int n0 = blockIdx.x * BN;
    if (causal && n0 > m0 + BM - 1) return;

    int z = blockIdx.z, z1 = z / zdiv, z2 = z - z1 * zdiv;
    A += z1 * sA1 + z2 * sA2;
    B += z1 * sB1 + z2 * sB2;
    long long oC = z1 * sC1 + z2 * sC2;

    int tid  = threadIdx.x;
    int lane = tid & 31;
    int w    = tid >> 5;
    int g    = lane >> 2, tg = lane & 3;
    int wm   = (w & 3) * 32;            // warp row offset in tile
    int wn   = (w >> 2) * (BN / 2);     // warp col offset in tile

    float acc[2][NT][4];
    #pragma unroll
    for (int mt = 0; mt < 2; mt++)
        #pragma unroll
        for (int nt = 0; nt < NT; nt++)
            #pragma unroll
            for (int i = 0; i < 4; i++) acc[mt][nt][i] = 0.f;

    int Keff = K;
    if (causalK && m0 + BM < K) Keff = m0 + BM;   // P[t][s] == 0 for s > t
    int nslab = Keff / BK;

    auto loadSlab = [&](int buf, int slab) {
        float* As = sm + buf * STW;
        float* Bs = As + AS;
        int ko = slab * BK;
        #pragma unroll
        for (int i = 0; i < (BM * 8) / 256; i++) {           // A: 128 x 8 float4
            int c = tid + i * 256;
            int r = c >> 3, f = (c & 7) * 4;
            cpa16(&As[r * AW + f], A + (long long)(m0 + r) * lda + ko + f);
        }
        if (TB) {
            #pragma unroll
            for (int i = 0; i < (BN * 8) / 256; i++) {       // B: BN x 8 float4
                int c = tid + i * 256;
                int r = c >> 3, f = (c & 7) * 4;
                cpa16(&Bs[r * BW + f], B + (long long)(n0 + r) * ldb + ko + f);
            }
        } else {
            #pragma unroll
            for (int i = 0; i < (BK * (BN / 4)) / 256; i++) { // B: 32 x (BN/4) float4
                int c = tid + i * 256;
                int r = c / (BN / 4), f = (c % (BN / 4)) * 4;
                cpa16(&Bs[r * BW + f], B + (long long)(ko + r) * ldb + n0 + f);
            }
        }
        asm volatile("cp.async.commit_group;" ::: "memory");
    };

    auto compute = [&](int buf) {
        const float* As = sm + buf * STW;
        const float* Bs = As + AS;
        #pragma unroll
        for (int kk = 0; kk < 4; kk++) {
            int k = kk * 8;
            uint32_t af[2][4];
            #pragma unroll
            for (int mt = 0; mt < 2; mt++) {
                int r = wm + mt * 16 + g;
                af[mt][0] = f2tf(As[r * AW + k + tg]);
                af[mt][1] = f2tf(As[(r + 8) * AW + k + tg]);
                af[mt][2] = f2tf(As[r * AW + k + tg + 4]);
                af[mt][3] = f2tf(As[(r + 8) * AW + k + tg + 4]);
            }
            #pragma unroll
            for (int nt = 0; nt < NT; nt++) {
                int cn = wn + nt * 8 + g;
                uint32_t b0, b1;
                if (TB) {
                    b0 = f2tf(Bs[cn * BW + k + tg]);
                    b1 = f2tf(Bs[cn * BW + k + tg + 4]);
                } else {
                    b0 = f2tf(Bs[(k + tg) * BW + cn]);
                    b1 = f2tf(Bs[(k + tg + 4) * BW + cn]);
                }
                #pragma unroll
                for (int mt = 0; mt < 2; mt++)
                    mma8(acc[mt][nt], af[mt], b0, b1);
            }
        }
    };

    loadSlab(0, 0);
    for (int s = 0; s < nslab; s++) {
        if (s + 1 < nslab) {
            loadSlab((s + 1) & 1, s + 1);
            asm volatile("cp.async.wait_group 1;" ::: "memory");
        } else {
            asm volatile("cp.async.wait_group 0;" ::: "memory");
        }
        __syncthreads();
        compute(s & 1);
        __syncthreads();
    }

    // Epilogue
    float* Cb = C + oC;
    const float* Rb = resid ? resid + oC : nullptr;
    #pragma unroll
    for (int mt = 0; mt < 2; mt++) {
        #pragma unroll
        for (int nt = 0; nt < NT; nt++) {
            int cn = n0 + wn + nt * 8 + 2 * tg;
            float bv0 = 0.f, bv1 = 0.f, s0 = 1.f, s1 = 1.f;
            if (bias) { bv0 = bias[cn]; bv1 = bias[cn + 1]; }
            if (pds) {
                float p0 = pds[cn & (HD - 1)], p1 = pds[(cn + 1) & (HD - 1)];
                float sp0 = (p0 > 20.f) ? p0 : log1pf(expf(p0));
                float sp1 = (p1 > 20.f) ? p1 : log1pf(expf(p1));
                s0 = 0.1803368801111f * sp0;   // log2(e)/sqrt(64) * softplus
                s1 = 0.1803368801111f * sp1;
            }
            #pragma unroll
            for (int h = 0; h < 2; h++) {
                int r = m0 + wm + mt * 16 + g + h * 8;
                float v0 = acc[mt][nt][h * 2 + 0];
                float v1 = acc[mt][nt][h * 2 + 1];
                if (bias) { v0 += bv0; v1 += bv1; }
                if (pds)  { v0 *= s0; v1 *= s1; }
                if (relu) { v0 = fmaxf(v0, 0.f); v1 = fmaxf(v1, 0.f); }
                long long off = (long long)r * ldc + cn;
                if (Rb) {
                    float2 rr = *reinterpret_cast<const float2*>(Rb + off);
                    v0 += rr.x; v1 += rr.y;
                }
                *reinterpret_cast<float2*>(Cb + off) = make_float2(v0, v1);
            }
        }
    }
}

// ----------------------------------------------------------------------------
// Elementwise kernels (proven in R1)
// ----------------------------------------------------------------------------
__device__ __forceinline__ float warpSum(float v) {
    #pragma unroll
    for (int o = 16; o > 0; o >>= 1) v += __shfl_xor_sync(0xffffffffu, v, o);
    return v;
}
__device__ __forceinline__ float warpMax(float v) {
    #pragma unroll
    for (int o = 16; o > 0; o >>= 1) v = fmaxf(v, __shfl_xor_sync(0xffffffffu, v, o));
    return v;
}

__global__ void __launch_bounds__(256) rmsnorm_k(const float* __restrict__ x,
                                                 const float* __restrict__ g,
                                                 float* __restrict__ out) {
    size_t base = (size_t)blockIdx.x * Dm;
    int tid = threadIdx.x;
    float4 xv = reinterpret_cast<const float4*>(x + base)[tid];
    float ss = xv.x * xv.x + xv.y * xv.y + xv.z * xv.z + xv.w * xv.w;
    __shared__ float sh[8];
    __shared__ float bval;
    ss = warpSum(ss);
    if ((tid & 31) == 0) sh[tid >> 5] = ss;
    __syncthreads();
    if (tid == 0) {
        float s = 0.f;
        #pragma unroll
        for (int i = 0; i < 8; i++) s += sh[i];
        bval = s;
    }
    __syncthreads();
    float r = rsqrtf(bval * (1.0f / Dm) + 1e-6f);
    float4 gv = reinterpret_cast<const float4*>(g)[tid];
    reinterpret_cast<float4*>(out + base)[tid] =
        make_float4(xv.x * r * gv.x, xv.y * r * gv.y, xv.z * r * gv.z, xv.w * r * gv.w);
}

__global__ void __launch_bounds__(256) layernorm_k(const float* __restrict__ x,
                                                   const float* __restrict__ gamma,
                                                   const float* __restrict__ beta,
                                                   float* __restrict__ out) {
    size_t base = (size_t)blockIdx.x * Dm;
    int tid = threadIdx.x;
    float4 xv = reinterpret_cast<const float4*>(x + base)[tid];
    float s1 = xv.x + xv.y + xv.z + xv.w;
    float s2 = xv.x * xv.x + xv.y * xv.y + xv.z * xv.z + xv.w * xv.w;
    __shared__ float shA[8], shB[8];
    __shared__ float bm, bv2;
    s1 = warpSum(s1);
    s2 = warpSum(s2);
    if ((tid & 31) == 0) { shA[tid >> 5] = s1; shB[tid >> 5] = s2; }
    __syncthreads();
    if (tid == 0) {
        float a = 0.f, b = 0.f;
        #pragma unroll
        for (int i = 0; i < 8; i++) { a += shA[i]; b += shB[i]; }
        bm = a * (1.0f / Dm); bv2 = b * (1.0f / Dm);
    }
    __syncthreads();
    float mean = bm;
    float r = rsqrtf(bv2 - mean * mean + 1e-5f);
    float4 gv = reinterpret_cast<const float4*>(gamma)[tid];
    float4 bvv = reinterpret_cast<const float4*>(beta)[tid];
    reinterpret_cast<float4*>(out + base)[tid] =
        make_float4((xv.x - mean) * r * gv.x + bvv.x, (xv.y - mean) * r * gv.y + bvv.y,
                    (xv.z - mean) * r * gv.z + bvv.z, (xv.w - mean) * r * gv.w + bvv.w);
}

__global__ void __launch_bounds__(256) softmax_k(float* __restrict__ sc,
                                                 const float* __restrict__ padding) {
    int t = blockIdx.x;
    int z = blockIdx.y;
    int b = z >> 4;
    float* row = sc + ((size_t)z * T + t) * T;
    int tid = threadIdx.x;
    int s0 = tid * 4;
    float4 rv = reinterpret_cast<float4*>(row)[tid];
    float4 pv = reinterpret_cast<const float4*>(padding + (size_t)b * T)[tid];
    float padt = padding[(size_t)b * T + t];
    float vals[4] = {rv.x, rv.y, rv.z, rv.w};
    float pads[4] = {pv.x, pv.y, pv.z, pv.w};
    float mx = -3.4e38f;
    #pragma unroll
    for (int i = 0; i < 4; i++) {
        bool ok = (s0 + i <= t) && (padt != 0.f) && (pads[i] != 0.f);
        vals[i] = ok ? vals[i] : -1e9f;
        mx = fmaxf(mx, vals[i]);
    }
    __shared__ float sh[8];
    __shared__ float bmax, bsum;
    mx = warpMax(mx);
    if ((tid & 31) == 0) sh[tid >> 5] = mx;
    __syncthreads();
    if (tid == 0) {
        float m = sh[0];
        #pragma unroll
        for (int i = 1; i < 8; i++) m = fmaxf(m, sh[i]);
        bmax = m;
    }
    __syncthreads();
    mx = bmax;
    float e[4], ls = 0.f;
    #pragma unroll
    for (int i = 0; i < 4; i++) { e[i] = __expf(vals[i] - mx); ls += e[i]; }
    ls = warpSum(ls);
    if ((tid & 31) == 0) sh[tid >> 5] = ls;
    __syncthreads();
    if (tid == 0) {
        float s = 0.f;
        #pragma unroll
        for (int i = 0; i < 8; i++) s += sh[i];
        bsum = s;
    }
    __syncthreads();
    float inv = 1.0f / bsum;
    reinterpret_cast<float4*>(row)[tid] =
        make_float4(e[0] * inv, e[1] * inv, e[2] * inv, e[3] * inv);
}

// ----------------------------------------------------------------------------
// Launch
// ----------------------------------------------------------------------------
extern "C" void kernel_launch(void* const* d_in, const int* in_sizes, int n_in,
                              void* d_out, int out_size) {
    const float* x    = (const float*)d_in[0];
    const float* pad  = (const float*)d_in[1];
    const float* rmss = (const float*)d_in[2];
    const float* pds  = (const float*)d_in[3];
    const float* wq   = (const float*)d_in[4];
    const float* bq   = (const float*)d_in[5];
    const float* wk   = (const float*)d_in[6];
    const float* bk   = (const float*)d_in[7];
    const float* wv   = (const float*)d_in[8];
    const float* bv   = (const float*)d_in[9];
    const float* wo   = (const float*)d_in[10];
    const float* bo   = (const float*)d_in[11];
    const float* lng  = (const float*)d_in[12];
    const float* lnb  = (const float*)d_in[13];
    const float* w1   = (const float*)d_in[14];
    const float* b1   = (const float*)d_in[15];
    const float* w2   = (const float*)d_in[16];
    const float* b2   = (const float*)d_in[17];
    float* out = (float*)d_out;

    float *xn, *q, *k, *v, *sc, *ao, *at, *ln, *h1;
    cudaGetSymbolAddress((void**)&xn, g_xn);
    cudaGetSymbolAddress((void**)&q,  g_q);
    cudaGetSymbolAddress((void**)&k,  g_k);
    cudaGetSymbolAddress((void**)&v,  g_v);
    cudaGetSymbolAddress((void**)&sc, g_sc);
    cudaGetSymbolAddress((void**)&ao, g_ao);
    cudaGetSymbolAddress((void**)&at, g_at);
    cudaGetSymbolAddress((void**)&ln, g_ln);
    cudaGetSymbolAddress((void**)&h1, g_h1);

    // Dynamic smem sizes (bytes) per instantiation
    const int SMF128 = (BM * 36 + BK * 136) * 2 * 4;   // <128,false> : 71680
    const int SMT128 = (BM * 36 + 128 * 36) * 2 * 4;   // <128,true>  : 73728
    const int SMF64  = (BM * 36 + BK * 72) * 2 * 4;    // <64,false>  : 55296
    cudaFuncSetAttribute(gemm_mma<128, false>, cudaFuncAttributeMaxDynamicSharedMemorySize, SMF128);
    cudaFuncSetAttribute(gemm_mma<128, true>,  cudaFuncAttributeMaxDynamicSharedMemorySize, SMT128);
    cudaFuncSetAttribute(gemm_mma<64,  false>, cudaFuncAttributeMaxDynamicSharedMemorySize, SMF64);

    const long long Z = 0;

    // 1. RMSNorm
    rmsnorm_k<<<MTOK, 256>>>(x, rmss, xn);

    // 2. Q/K/V projections (Q fuses bias + per-dim softplus scale)
    gemm_mma<128, false><<<dim3(Dm / 128, MTOK / 128, 1), 256, SMF128>>>(
        xn, wq, q, Dm, Dm, Dm, Dm, 1, Z, Z, Z, Z, Z, Z, bq, nullptr, pds, 0, 0, 0);
    gemm_mma<128, false><<<dim3(Dm / 128, MTOK / 128, 1), 256, SMF128>>>(
        xn, wk, k, Dm, Dm, Dm, Dm, 1, Z, Z, Z, Z, Z, Z, bk, nullptr, nullptr, 0, 0, 0);
    gemm_mma<128, false><<<dim3(Dm / 128, MTOK / 128, 1), 256, SMF128>>>(
        xn, wv, v, Dm, Dm, Dm, Dm, 1, Z, Z, Z, Z, Z, Z, bv, nullptr, nullptr, 0, 0, 0);

    // 3. scores[b,n,t,s] = Q K^T (batched over b,n; causal tile skip)
    gemm_mma<128, true><<<dim3(T / 128, T / 128, Bb * NH), 256, SMT128>>>(
        q, k, sc, HD, Dm, Dm, T, NH,
        (long long)T * Dm, (long long)HD,
        (long long)T * Dm, (long long)HD,
        (long long)NH * T * T, (long long)T * T,
        nullptr, nullptr, nullptr, 0, 1, 0);

    // 4. masked softmax (causal + padding), in place
    softmax_k<<<dim3(T, Bb * NH), 256>>>(sc, pad);

    // 5. attn_out[b,t,n,h] = P V (batched over b,n; K clamped to diagonal)
    gemm_mma<64, false><<<dim3(1, T / 128, Bb * NH), 256, SMF64>>>(
        sc, v, ao, T, T, Dm, Dm, NH,
        (long long)NH * T * T, (long long)T * T,
        (long long)T * Dm, (long long)HD,
        (long long)T * Dm, (long long)HD,
        nullptr, nullptr, nullptr, 0, 0, 1);

    // 6. out-proj + bo + residual(x)
    gemm_mma<128, true><<<dim3(Dm / 128, MTOK / 128, 1), 256, SMT128>>>(
        ao, wo, at, Dm, Dm, Dm, Dm, 1, Z, Z, Z, Z, Z, Z, bo, x, nullptr, 0, 0, 0);

    // 7. LayerNorm
    layernorm_k<<<MTOK, 256>>>(at, lng, lnb, ln);

    // 8. FFN1 + ReLU
    gemm_mma<128, false><<<dim3(FF / 128, MTOK / 128, 1), 256, SMF128>>>(
        ln, w1, h1, Dm, Dm, FF, FF, 1, Z, Z, Z, Z, Z, Z, b1, nullptr, nullptr, 1, 0, 0);

    // 9. FFN2 + b2 + residual(at) -> out
    gemm_mma<128, false><<<dim3(Dm / 128, MTOK / 128, 1), 256, SMF128>>>(
        h1, w2, out, FF, FF, Dm, Dm, 1, Z, Z, Z, Z, Z, Z, b2, at, nullptr, 0, 0, 0);
}

// round 7
// speedup vs baseline: 3.5494x; 1.2066x over previous
#include <cuda_runtime.h>
#include <math.h>
#include <stdint.h>

// Problem constants
constexpr int Bb   = 8;
constexpr int T    = 1024;
constexpr int Dm   = 1024;
constexpr int NH   = 16;
constexpr int HD   = 64;
constexpr int FF   = 4096;
constexpr int MTOK = Bb * T;            // 8192 tokens

// ----------------------------------------------------------------------------
// Scratch (allocation-free: __device__ globals)
// ----------------------------------------------------------------------------
__device__ __align__(256) float g_xn[(size_t)MTOK * Dm];
__device__ __align__(256) float g_q [(size_t)MTOK * Dm];
__device__ __align__(256) float g_k [(size_t)MTOK * Dm];
__device__ __align__(256) float g_v [(size_t)MTOK * Dm];
__device__ __align__(256) float g_sc[(size_t)Bb * NH * T * T];   // 512 MB scores
__device__ __align__(256) float g_ao[(size_t)MTOK * Dm];
__device__ __align__(256) float g_at[(size_t)MTOK * Dm];
__device__ __align__(256) float g_ln[(size_t)MTOK * Dm];
__device__ __align__(256) float g_h1[(size_t)MTOK * FF];

// ----------------------------------------------------------------------------
// Baseline-PTX helpers (no 'a'-gated instructions — harness compiles compute_103)
// ----------------------------------------------------------------------------
__device__ __forceinline__ uint32_t smem_u32(const void* p) {
    uint32_t a;
    asm("{ .reg .u64 t; cvta.to.shared.u64 t, %1; cvt.u32.u64 %0, t; }" : "=r"(a) : "l"(p));
    return a;
}
__device__ __forceinline__ void cpa16(void* dst, const void* src) {
    uint32_t d = smem_u32(dst);
    asm volatile("cp.async.cg.shared.global [%0], [%1], 16;" :: "r"(d), "l"(src) : "memory");
}
// TF32 fast path: HMMA.TF32 reads only the top 19 bits of the register —
// pass raw fp32 bits (truncation rounding), no cvt instruction needed.
__device__ __forceinline__ uint32_t f2tf(float f) {
    return __float_as_uint(f);
}
__device__ __forceinline__ void mma8(float* c, const uint32_t* a, uint32_t b0, uint32_t b1) {
    asm volatile(
        "mma.sync.aligned.m16n8k8.row.col.f32.tf32.tf32.f32 "
        "{%0,%1,%2,%3}, {%4,%5,%6,%7}, {%8,%9}, {%0,%1,%2,%3};"
        : "+f"(c[0]), "+f"(c[1]), "+f"(c[2]), "+f"(c[3])
        : "r"(a[0]), "r"(a[1]), "r"(a[2]), "r"(a[3]), "r"(b0), "r"(b1));
}

// ----------------------------------------------------------------------------
// Tensor-core (mma.sync tf32) GEMM
// C[128 x BN] per CTA, K slab 32, double-buffered cp.async.
// A row-major [m][k]. B: TB=false -> B[k][n] (ldb); TB=true -> B[n][k] (ldb).
// Two-level batch z -> (z/zdiv, z%zdiv) with elementwise strides.
// Epilogue: +bias[n], *softplus-q-scale(n&63), ReLU, +resid (C-strided).
// causal:   skip C tiles fully above the diagonal (scores GEMM).
// causalK:  clamp K loop to m0+BM (PV GEMM; P is exactly 0 for s > t).
// ----------------------------------------------------------------------------
constexpr int BM = 128;
constexpr int BK = 32;

template <int BN, bool TB>
__global__ void __launch_bounds__(256, 2) gemm_mma(
    const float* __restrict__ A, const float* __restrict__ B, float* __restrict__ C,
    int K, int lda, int ldb, int ldc, int zdiv,
    long long sA1, long long sA2, long long sB1, long long sB2,
    long long sC1, long long sC2,
    const float* __restrict__ bias, const float* __restrict__ resid,
    const float* __restrict__ pds, int relu, int causal, int causalK)
{
    constexpr int AW = BK + 4;                 // A row words (pad 4 -> conflict-free frags)
    constexpr int BW = TB ? (BK + 4) : (BN + 8);
    constexpr int AS = BM * AW;
    constexpr int BS = TB ? BN * BW : BK * BW;
    constexpr int STW = AS + BS;               // words per stage
    constexpr int NT = BN / 16;                // n-tiles per warp (warp covers BN/2 cols)
    extern __shared__ float sm[];

    int m0 = blockIdx.y * BM;
    int n0 = blockIdx.x * BN;
    if (causal && n0 > m0 + BM - 1) return;

    int z = blockIdx.z, z1 = z / zdiv, z2 = z - z1 * zdiv;
    A += z1 * sA1 + z2 * sA2;
    B += z1 * sB1 + z2 * sB2;
    long long oC = z1 * sC1 + z2 * sC2;

    int tid  = threadIdx.x;
    int lane = tid & 31;
    int w    = tid >> 5;
    int g    = lane >> 2, tg = lane & 3;
    int wm   = (w & 3) * 32;            // warp row offset in tile
    int wn   = (w >> 2) * (BN / 2);     // warp col offset in tile

    float acc[2][NT][4];
    #pragma unroll
    for (int mt = 0; mt < 2; mt++)
        #pragma unroll
        for (int nt = 0; nt < NT; nt++)
            #pragma unroll
            for (int i = 0; i < 4; i++) acc[mt][nt][i] = 0.f;

    int Keff = K;
    if (causalK && m0 + BM < K) Keff = m0 + BM;   // P[t][s] == 0 for s > t
    int nslab = Keff / BK;

    auto loadSlab = [&](int buf, int slab) {
        float* As = sm + buf * STW;
        float* Bs = As + AS;
        int ko = slab * BK;
        #pragma unroll
        for (int i = 0; i < (BM * 8) / 256; i++) {           // A: 128 x 8 float4
            int c = tid + i * 256;
            int r = c >> 3, f = (c & 7) * 4;
            cpa16(&As[r * AW + f], A + (long long)(m0 + r) * lda + ko + f);
        }
        if (TB) {
            #pragma unroll
            for (int i = 0; i < (BN * 8) / 256; i++) {       // B: BN x 8 float4
                int c = tid + i * 256;
                int r = c >> 3, f = (c & 7) * 4;
                cpa16(&Bs[r * BW + f], B + (long long)(n0 + r) * ldb + ko + f);
            }
        } else {
            #pragma unroll
            for (int i = 0; i < (BK * (BN / 4)) / 256; i++) { // B: 32 x (BN/4) float4
                int c = tid + i * 256;
                int r = c / (BN / 4), f = (c % (BN / 4)) * 4;
                cpa16(&Bs[r * BW + f], B + (long long)(ko + r) * ldb + n0 + f);
            }
        }
        asm volatile("cp.async.commit_group;" ::: "memory");
    };

    auto compute = [&](int buf) {
        const float* As = sm + buf * STW;
        const float* Bs = As + AS;
        #pragma unroll
        for (int kk = 0; kk < 4; kk++) {
            int k = kk * 8;
            uint32_t af[2][4];
            #pragma unroll
            for (int mt = 0; mt < 2; mt++) {
                int r = wm + mt * 16 + g;
                af[mt][0] = f2tf(As[r * AW + k + tg]);
                af[mt][1] = f2tf(As[(r + 8) * AW + k + tg]);
                af[mt][2] = f2tf(As[r * AW + k + tg + 4]);
                af[mt][3] = f2tf(As[(r + 8) * AW + k + tg + 4]);
            }
            #pragma unroll
            for (int nt = 0; nt < NT; nt++) {
                int cn = wn + nt * 8 + g;
                uint32_t b0, b1;
                if (TB) {
                    b0 = f2tf(Bs[cn * BW + k + tg]);
                    b1 = f2tf(Bs[cn * BW + k + tg + 4]);
                } else {
                    b0 = f2tf(Bs[(k + tg) * BW + cn]);
                    b1 = f2tf(Bs[(k + tg + 4) * BW + cn]);
                }
                #pragma unroll
                for (int mt = 0; mt < 2; mt++)
                    mma8(acc[mt][nt], af[mt], b0, b1);
            }
        }
    };

    loadSlab(0, 0);
    for (int s = 0; s < nslab; s++) {
        if (s + 1 < nslab) {
            loadSlab((s + 1) & 1, s + 1);
            asm volatile("cp.async.wait_group 1;" ::: "memory");
        } else {
            asm volatile("cp.async.wait_group 0;" ::: "memory");
        }
        __syncthreads();
        compute(s & 1);
        __syncthreads();
    }

    // Epilogue
    float* Cb = C + oC;
    const float* Rb = resid ? resid + oC : nullptr;
    #pragma unroll
    for (int mt = 0; mt < 2; mt++) {
        #pragma unroll
        for (int nt = 0; nt < NT; nt++) {
            int cn = n0 + wn + nt * 8 + 2 * tg;
            float bv0 = 0.f, bv1 = 0.f, s0 = 1.f, s1 = 1.f;
            if (bias) { bv0 = bias[cn]; bv1 = bias[cn + 1]; }
            if (pds) {
                float p0 = pds[cn & (HD - 1)], p1 = pds[(cn + 1) & (HD - 1)];
                float sp0 = (p0 > 20.f) ? p0 : log1pf(expf(p0));
                float sp1 = (p1 > 20.f) ? p1 : log1pf(expf(p1));
                s0 = 0.1803368801111f * sp0;   // log2(e)/sqrt(64) * softplus
                s1 = 0.1803368801111f * sp1;
            }
            #pragma unroll
            for (int h = 0; h < 2; h++) {
                int r = m0 + wm + mt * 16 + g + h * 8;
                float v0 = acc[mt][nt][h * 2 + 0];
                float v1 = acc[mt][nt][h * 2 + 1];
                if (bias) { v0 += bv0; v1 += bv1; }
                if (pds)  { v0 *= s0; v1 *= s1; }
                if (relu) { v0 = fmaxf(v0, 0.f); v1 = fmaxf(v1, 0.f); }
                long long off = (long long)r * ldc + cn;
                if (Rb) {
                    float2 rr = *reinterpret_cast<const float2*>(Rb + off);
                    v0 += rr.x; v1 += rr.y;
                }
                *reinterpret_cast<float2*>(Cb + off) = make_float2(v0, v1);
            }
        }
    }
}

// ----------------------------------------------------------------------------
// Elementwise kernels (proven in R1)
// ----------------------------------------------------------------------------
__device__ __forceinline__ float warpSum(float v) {
    #pragma unroll
    for (int o = 16; o > 0; o >>= 1) v += __shfl_xor_sync(0xffffffffu, v, o);
    return v;
}
__device__ __forceinline__ float warpMax(float v) {
    #pragma unroll
    for (int o = 16; o > 0; o >>= 1) v = fmaxf(v, __shfl_xor_sync(0xffffffffu, v, o));
    return v;
}

__global__ void __launch_bounds__(256) rmsnorm_k(const float* __restrict__ x,
                                                 const float* __restrict__ g,
                                                 float* __restrict__ out) {
    size_t base = (size_t)blockIdx.x * Dm;
    int tid = threadIdx.x;
    float4 xv = reinterpret_cast<const float4*>(x + base)[tid];
    float ss = xv.x * xv.x + xv.y * xv.y + xv.z * xv.z + xv.w * xv.w;
    __shared__ float sh[8];
    __shared__ float bval;
    ss = warpSum(ss);
    if ((tid & 31) == 0) sh[tid >> 5] = ss;
    __syncthreads();
    if (tid == 0) {
        float s = 0.f;
        #pragma unroll
        for (int i = 0; i < 8; i++) s += sh[i];
        bval = s;
    }
    __syncthreads();
    float r = rsqrtf(bval * (1.0f / Dm) + 1e-6f);
    float4 gv = reinterpret_cast<const float4*>(g)[tid];
    reinterpret_cast<float4*>(out + base)[tid] =
        make_float4(xv.x * r * gv.x, xv.y * r * gv.y, xv.z * r * gv.z, xv.w * r * gv.w);
}

__global__ void __launch_bounds__(256) layernorm_k(const float* __restrict__ x,
                                                   const float* __restrict__ gamma,
                                                   const float* __restrict__ beta,
                                                   float* __restrict__ out) {
    size_t base = (size_t)blockIdx.x * Dm;
    int tid = threadIdx.x;
    float4 xv = reinterpret_cast<const float4*>(x + base)[tid];
    float s1 = xv.x + xv.y + xv.z + xv.w;
    float s2 = xv.x * xv.x + xv.y * xv.y + xv.z * xv.z + xv.w * xv.w;
    __shared__ float shA[8], shB[8];
    __shared__ float bm, bv2;
    s1 = warpSum(s1);
    s2 = warpSum(s2);
    if ((tid & 31) == 0) { shA[tid >> 5] = s1; shB[tid >> 5] = s2; }
    __syncthreads();
    if (tid == 0) {
        float a = 0.f, b = 0.f;
        #pragma unroll
        for (int i = 0; i < 8; i++) { a += shA[i]; b += shB[i]; }
        bm = a * (1.0f / Dm); bv2 = b * (1.0f / Dm);
    }
    __syncthreads();
    float mean = bm;
    float r = rsqrtf(bv2 - mean * mean + 1e-5f);
    float4 gv = reinterpret_cast<const float4*>(gamma)[tid];
    float4 bvv = reinterpret_cast<const float4*>(beta)[tid];
    reinterpret_cast<float4*>(out + base)[tid] =
        make_float4((xv.x - mean) * r * gv.x + bvv.x, (xv.y - mean) * r * gv.y + bvv.y,
                    (xv.z - mean) * r * gv.z + bvv.z, (xv.w - mean) * r * gv.w + bvv.w);
}

__global__ void __launch_bounds__(256) softmax_k(float* __restrict__ sc,
                                                 const float* __restrict__ padding) {
    int t = blockIdx.x;
    int z = blockIdx.y;
    int b = z >> 4;
    float* row = sc + ((size_t)z * T + t) * T;
    int tid = threadIdx.x;
    int s0 = tid * 4;
    float4 rv = reinterpret_cast<float4*>(row)[tid];
    float4 pv = reinterpret_cast<const float4*>(padding + (size_t)b * T)[tid];
    float padt = padding[(size_t)b * T + t];
    float vals[4] = {rv.x, rv.y, rv.z, rv.w};
    float pads[4] = {pv.x, pv.y, pv.z, pv.w};
    float mx = -3.4e38f;
    #pragma unroll
    for (int i = 0; i < 4; i++) {
        bool ok = (s0 + i <= t) && (padt != 0.f) && (pads[i] != 0.f);
        vals[i] = ok ? vals[i] : -1e9f;
        mx = fmaxf(mx, vals[i]);
    }
    __shared__ float sh[8];
    __shared__ float bmax, bsum;
    mx = warpMax(mx);
    if ((tid & 31) == 0) sh[tid >> 5] = mx;
    __syncthreads();
    if (tid == 0) {
        float m = sh[0];
        #pragma unroll
        for (int i = 1; i < 8; i++) m = fmaxf(m, sh[i]);
        bmax = m;
    }
    __syncthreads();
    mx = bmax;
    float e[4], ls = 0.f;
    #pragma unroll
    for (int i = 0; i < 4; i++) { e[i] = __expf(vals[i] - mx); ls += e[i]; }
    ls = warpSum(ls);
    if ((tid & 31) == 0) sh[tid >> 5] = ls;
    __syncthreads();
    if (tid == 0) {
        float s = 0.f;
        #pragma unroll
        for (int i = 0; i < 8; i++) s += sh[i];
        bsum = s;
    }
    __syncthreads();
    float inv = 1.0f / bsum;
    reinterpret_cast<float4*>(row)[tid] =
        make_float4(e[0] * inv, e[1] * inv, e[2] * inv, e[3] * inv);
}

// ----------------------------------------------------------------------------
// Launch
// ----------------------------------------------------------------------------
extern "C" void kernel_launch(void* const* d_in, const int* in_sizes, int n_in,
                              void* d_out, int out_size) {
    const float* x    = (const float*)d_in[0];
    const float* pad  = (const float*)d_in[1];
    const float* rmss = (const float*)d_in[2];
    const float* pds  = (const float*)d_in[3];
    const float* wq   = (const float*)d_in[4];
    const float* bq   = (const float*)d_in[5];
    const float* wk   = (const float*)d_in[6];
    const float* bk   = (const float*)d_in[7];
    const float* wv   = (const float*)d_in[8];
    const float* bv   = (const float*)d_in[9];
    const float* wo   = (const float*)d_in[10];
    const float* bo   = (const float*)d_in[11];
    const float* lng  = (const float*)d_in[12];
    const float* lnb  = (const float*)d_in[13];
    const float* w1   = (const float*)d_in[14];
    const float* b1   = (const float*)d_in[15];
    const float* w2   = (const float*)d_in[16];
    const float* b2   = (const float*)d_in[17];
    float* out = (float*)d_out;

    float *xn, *q, *k, *v, *sc, *ao, *at, *ln, *h1;
    cudaGetSymbolAddress((void**)&xn, g_xn);
    cudaGetSymbolAddress((void**)&q,  g_q);
    cudaGetSymbolAddress((void**)&k,  g_k);
    cudaGetSymbolAddress((void**)&v,  g_v);
    cudaGetSymbolAddress((void**)&sc, g_sc);
    cudaGetSymbolAddress((void**)&ao, g_ao);
    cudaGetSymbolAddress((void**)&at, g_at);
    cudaGetSymbolAddress((void**)&ln, g_ln);
    cudaGetSymbolAddress((void**)&h1, g_h1);

    // Dynamic smem sizes (bytes) per instantiation
    const int SMF128 = (BM * 36 + BK * 136) * 2 * 4;   // <128,false> : 71680
    const int SMT128 = (BM * 36 + 128 * 36) * 2 * 4;   // <128,true>  : 73728
    const int SMF64  = (BM * 36 + BK * 72) * 2 * 4;    // <64,false>  : 55296
    cudaFuncSetAttribute(gemm_mma<128, false>, cudaFuncAttributeMaxDynamicSharedMemorySize, SMF128);
    cudaFuncSetAttribute(gemm_mma<128, true>,  cudaFuncAttributeMaxDynamicSharedMemorySize, SMT128);
    cudaFuncSetAttribute(gemm_mma<64,  false>, cudaFuncAttributeMaxDynamicSharedMemorySize, SMF64);

    const long long Z = 0;

    // 1. RMSNorm
    rmsnorm_k<<<MTOK, 256>>>(x, rmss, xn);

    // 2. Q/K/V projections (Q fuses bias + per-dim softplus scale)
    gemm_mma<128, false><<<dim3(Dm / 128, MTOK / 128, 1), 256, SMF128>>>(
        xn, wq, q, Dm, Dm, Dm, Dm, 1, Z, Z, Z, Z, Z, Z, bq, nullptr, pds, 0, 0, 0);
    gemm_mma<128, false><<<dim3(Dm / 128, MTOK / 128, 1), 256, SMF128>>>(
        xn, wk, k, Dm, Dm, Dm, Dm, 1, Z, Z, Z, Z, Z, Z, bk, nullptr, nullptr, 0, 0, 0);
    gemm_mma<128, false><<<dim3(Dm / 128, MTOK / 128, 1), 256, SMF128>>>(
        xn, wv, v, Dm, Dm, Dm, Dm, 1, Z, Z, Z, Z, Z, Z, bv, nullptr, nullptr, 0, 0, 0);

    // 3. scores[b,n,t,s] = Q K^T (batched over b,n; causal tile skip)
    gemm_mma<128, true><<<dim3(T / 128, T / 128, Bb * NH), 256, SMT128>>>(
        q, k, sc, HD, Dm, Dm, T, NH,
        (long long)T * Dm, (long long)HD,
        (long long)T * Dm, (long long)HD,
        (long long)NH * T * T, (long long)T * T,
        nullptr, nullptr, nullptr, 0, 1, 0);

    // 4. masked softmax (causal + padding), in place
    softmax_k<<<dim3(T, Bb * NH), 256>>>(sc, pad);

    // 5. attn_out[b,t,n,h] = P V (batched over b,n; K clamped to diagonal)
    gemm_mma<64, false><<<dim3(1, T / 128, Bb * NH), 256, SMF64>>>(
        sc, v, ao, T, T, Dm, Dm, NH,
        (long long)NH * T * T, (long long)T * T,
        (long long)T * Dm, (long long)HD,
        (long long)T * Dm, (long long)HD,
        nullptr, nullptr, nullptr, 0, 0, 1);

    // 6. out-proj + bo + residual(x)
    gemm_mma<128, true><<<dim3(Dm / 128, MTOK / 128, 1), 256, SMT128>>>(
        ao, wo, at, Dm, Dm, Dm, Dm, 1, Z, Z, Z, Z, Z, Z, bo, x, nullptr, 0, 0, 0);

    // 7. LayerNorm
    layernorm_k<<<MTOK, 256>>>(at, lng, lnb, ln);

    // 8. FFN1 + ReLU
    gemm_mma<128, false><<<dim3(FF / 128, MTOK / 128, 1), 256, SMF128>>>(
        ln, w1, h1, Dm, Dm, FF, FF, 1, Z, Z, Z, Z, Z, Z, b1, nullptr, nullptr, 1, 0, 0);

    // 9. FFN2 + b2 + residual(at) -> out
    gemm_mma<128, false><<<dim3(Dm / 128, MTOK / 128, 1), 256, SMF128>>>(
        h1, w2, out, FF, FF, Dm, Dm, 1, Z, Z, Z, Z, Z, Z, b2, at, nullptr, 0, 0, 0);
}